// round 16
// baseline (speedup 1.0000x reference)
#include <cuda_runtime.h>
#include <cuda_bf16.h>
#include <stdint.h>

#define NNODES 8192
#define DIM    256
#define ALPHA  3.0f
#define NEG    0.2f

#define TPB    256
#define CPT    (NNODES / TPB)     // 32 columns per thread
#define VEC4   (CPT / 4)          // 8 float4 groups
#define NBLK   740                // 5 blocks/SM x 148 SMs — ALL resident wave 1
#define NWARP  (TPB / 32)

// Scratch (__device__ globals; zero-init at load; no cudaMalloc)
__device__ float g_s1[NNODES];
__device__ float g_s2p[NNODES];   // permuted: g_s2p[idx[j]] = s2[j]
__device__ int   g_done;          // score-phase arrival counter
__device__ int   g_fin;           // finish counter (resets both)

// Single-op hardware tanh (sm_75+): MUFU.TANH, rel err ~2^-11
__device__ __forceinline__ float htanh(float x) {
    float y;
    asm("tanh.approx.f32 %0, %1;" : "=f"(y) : "f"(x));
    return y;
}

// ---------------------------------------------------------------------------
// Fused persistent kernel, grid = 740 (all resident -> spin is deadlock-free).
// Phase 1 (score): half-warp per node, R9 layout, spread over all blocks.
// Barrier: release fence + counter; consumers re-read via __ldcg (L2).
// Phase 2 (softmax): stage s2p -> SMEM once per block, then ~11 rows with the
// R13 measured-best body (one exp/element), s2 reads via LDS (zero L1 loads).
// ---------------------------------------------------------------------------
__global__ void __launch_bounds__(TPB, 5)
fused_kernel(const int* __restrict__ idx,
             const float* __restrict__ e1,
             const float* __restrict__ e2,
             const float* __restrict__ w,
             const float* __restrict__ att_b,
             float* __restrict__ out)
{
    const int bid = blockIdx.x;
    const int t   = threadIdx.x;

    // ---- phase 1: score ----
    {
        const int g   = bid * (TPB / 16) + (t >> 4);   // global half-warp id
        const int sub = t & 15;
        if (g < NNODES) {
            const int node = g;
            const int src  = __ldg(&idx[node]);
            const float4* r1 = (const float4*)(e1 + (size_t)src * DIM);
            const float4* r2 = (const float4*)(e2 + (size_t)src * DIM);
            const float4* w1 = (const float4*)(w);
            const float4* w2 = (const float4*)(w + DIM);

            float p1 = 0.f, p2 = 0.f;
            #pragma unroll
            for (int q = 0; q < 4; q++) {
                const int k = sub + 16 * q;            // interleaved -> coalesced
                float4 a  = r1[k];
                float4 b  = r2[k];
                float4 wa = __ldg(&w1[k]);
                float4 wb = __ldg(&w2[k]);
                p1 += htanh(ALPHA * a.x) * wa.x + htanh(ALPHA * a.y) * wa.y
                    + htanh(ALPHA * a.z) * wa.z + htanh(ALPHA * a.w) * wa.w;
                p2 += htanh(ALPHA * b.x) * wb.x + htanh(ALPHA * b.y) * wb.y
                    + htanh(ALPHA * b.z) * wb.z + htanh(ALPHA * b.w) * wb.w;
            }
            #pragma unroll
            for (int o = 8; o > 0; o >>= 1) {
                p1 += __shfl_xor_sync(0xffffffffu, p1, o);
                p2 += __shfl_xor_sync(0xffffffffu, p2, o);
            }
            if (sub == 0) {
                g_s1[node] = p1;
                g_s2p[src] = p2;
            }
        }
        __syncthreads();
        if (t == 0) {
            __threadfence();                 // release (one L1 flush per block)
            atomicAdd(&g_done, 1);
        }
    }

    // ---- barrier: all 740 blocks resident -> spin cannot deadlock ----
    if (t == 0) {
        volatile int* done = &g_done;
        while (*done < NBLK) __nanosleep(64);
    }
    __syncthreads();

    // ---- stage s2p into SMEM once (L2 reads via __ldcg, bypass L1) ----
    __shared__ float s2s[NNODES];            // 32 KB
    __shared__ float shs[NWARP];
    float4* s2s4 = (float4*)s2s;
    const float4* s2p4 = (const float4*)g_s2p;
    #pragma unroll
    for (int q = 0; q < VEC4; q++)
        s2s4[q * TPB + t] = __ldcg(&s2p4[q * TPB + t]);
    __syncthreads();

    const float bias = __ldg(att_b);

    // ---- phase 2: rows i = bid, bid+740, ... (R13 body, LDS source) ----
    for (int i = bid; i < NNODES; i += NBLK) {
        const float base = __ldcg(&g_s1[i]) + bias;

        float vals[CPT];
        float sum = 0.f;
        #pragma unroll
        for (int q = 0; q < VEC4; q++) {
            float4 s = s2s4[q * TPB + t];
            #pragma unroll
            for (int u = 0; u < 4; u++) {
                float x = base + ((const float*)&s)[u];
                x = (x > 0.f) ? x : NEG * x;          // leaky_relu
                float e = __expf(x);
                vals[q * 4 + u] = e;
                sum += e;
            }
        }

        #pragma unroll
        for (int o = 16; o > 0; o >>= 1)
            sum += __shfl_xor_sync(0xffffffffu, sum, o);
        if ((t & 31) == 0) shs[t >> 5] = sum;
        __syncthreads();
        sum = 0.f;
        #pragma unroll
        for (int wgi = 0; wgi < NWARP; wgi++) sum += shs[wgi];
        const float inv = __frcp_rn(sum);
        __syncthreads();                     // shs safe for next row

        float4* row4 = (float4*)(out + (size_t)i * NNODES);
        #pragma unroll
        for (int q = 0; q < VEC4; q++) {
            float4 v;
            v.x = vals[q * 4 + 0] * inv;
            v.y = vals[q * 4 + 1] * inv;
            v.z = vals[q * 4 + 2] * inv;
            v.w = vals[q * 4 + 3] * inv;
            row4[q * TPB + t] = v;
        }
    }

    // ---- epilogue: last block resets counters (graph-replay safe) ----
    __syncthreads();
    if (t == 0) {
        int f = atomicAdd(&g_fin, 1);
        if (f == NBLK - 1) {                 // everyone already passed the spin
            g_done = 0;
            g_fin  = 0;
            __threadfence();
        }
    }
}

// ---------------------------------------------------------------------------
// Inputs: idx[int32 N], emb1_w[f32 N*D], emb2_w[f32 N*D], att_w[f32 2D],
//         att_b[f32 1].  Output: f32 N*N.
// ---------------------------------------------------------------------------
extern "C" void kernel_launch(void* const* d_in, const int* in_sizes, int n_in,
                              void* d_out, int out_size)
{
    const int*   idx  = (const int*)  d_in[0];
    const float* e1   = (const float*)d_in[1];
    const float* e2   = (const float*)d_in[2];
    const float* attw = (const float*)d_in[3];
    const float* attb = (const float*)d_in[4];
    float*       out  = (float*)d_out;

    fused_kernel<<<NBLK, TPB>>>(idx, e1, e2, attw, attb, out);
}

// round 17
// speedup vs baseline: 1.2066x; 1.2066x over previous
#include <cuda_runtime.h>
#include <cuda_bf16.h>
#include <stdint.h>

#define NNODES 8192
#define DIM    256
#define ALPHA  3.0f
#define NEG    0.2f

#define TPB  256                 // softmax threads per block (measured-best)
#define CPT  (NNODES / TPB)      // 32 columns per thread
#define VEC4 (CPT / 4)           // 8 float4 groups per thread

// Scratch (__device__ globals; no cudaMalloc allowed)
__device__ float g_s1[NNODES];
__device__ float g_s2p[NNODES];  // permuted: g_s2p[idx[j]] = s2[j]

// Single-op hardware tanh (sm_75+): MUFU.TANH, rel err ~2^-11 (<< 1e-3 budget)
__device__ __forceinline__ float htanh(float x) {
    float y;
    asm("tanh.approx.f32 %0, %1;" : "=f"(y) : "f"(x));
    return y;
}

// ---------------------------------------------------------------------------
// score: HALF-WARP per node (16 lanes x 16 dims each) — R9 proven math,
// packed into 256-thread blocks (512 blocks). Early PDL trigger after the
// result stores so the softmax grid can begin launching sooner.
// ---------------------------------------------------------------------------
__global__ void __launch_bounds__(256)
score_kernel(const int* __restrict__ idx,
             const float* __restrict__ e1,
             const float* __restrict__ e2,
             const float* __restrict__ w)
{
    const int node = (blockIdx.x * 256 + threadIdx.x) >> 4;   // 16 nodes/block
    const int sub  = threadIdx.x & 15;
    const int src  = __ldg(&idx[node]);

    const float4* r1 = (const float4*)(e1 + (size_t)src * DIM);
    const float4* r2 = (const float4*)(e2 + (size_t)src * DIM);
    const float4* w1 = (const float4*)(w);
    const float4* w2 = (const float4*)(w + DIM);

    float p1 = 0.f, p2 = 0.f;
    #pragma unroll
    for (int q = 0; q < 4; q++) {
        const int k = sub + 16 * q;                 // interleaved -> coalesced
        float4 a  = r1[k];
        float4 b  = r2[k];
        float4 wa = __ldg(&w1[k]);
        float4 wb = __ldg(&w2[k]);
        p1 += htanh(ALPHA * a.x) * wa.x + htanh(ALPHA * a.y) * wa.y
            + htanh(ALPHA * a.z) * wa.z + htanh(ALPHA * a.w) * wa.w;
        p2 += htanh(ALPHA * b.x) * wb.x + htanh(ALPHA * b.y) * wb.y
            + htanh(ALPHA * b.z) * wb.z + htanh(ALPHA * b.w) * wb.w;
    }
    #pragma unroll
    for (int o = 8; o > 0; o >>= 1) {
        p1 += __shfl_xor_sync(0xffffffffu, p1, o);
        p2 += __shfl_xor_sync(0xffffffffu, p2, o);
    }
    if (sub == 0) {
        g_s1[node] = p1;
        g_s2p[src] = p2;
    }

    // signal downstream PDL launch as soon as this block's work is done
    cudaTriggerProgrammaticLaunchCompletion();
}

// ---------------------------------------------------------------------------
// softmax: one block per row i — R13 body UNCHANGED (at the store ceiling).
// ---------------------------------------------------------------------------
__global__ void __launch_bounds__(TPB)
softmax_kernel(const float* __restrict__ att_b,
               float* __restrict__ out)
{
    const int i = blockIdx.x;
    const int t = threadIdx.x;

    // pre-dependency prologue: pure address math / parameter loads
    const float bias   = __ldg(att_b);
    float4*     row4   = (float4*)(out + (size_t)i * NNODES);
    const float4* s2p4 = (const float4*)g_s2p;

    // wait for score_kernel completion (PDL); no-op if launched normally
    cudaGridDependencySynchronize();

    const float base = g_s1[i] + bias;

    float vals[CPT];
    float sum = 0.f;
    #pragma unroll
    for (int q = 0; q < VEC4; q++) {
        float4 s = __ldg(&s2p4[q * TPB + t]);
        #pragma unroll
        for (int u = 0; u < 4; u++) {
            float x = base + ((const float*)&s)[u];
            x = (x > 0.f) ? x : NEG * x;      // leaky_relu
            float e = __expf(x);
            vals[q * 4 + u] = e;
            sum += e;
        }
    }

    // block sum (8 warps)
    __shared__ float shs[TPB / 32];
    #pragma unroll
    for (int o = 16; o > 0; o >>= 1)
        sum += __shfl_xor_sync(0xffffffffu, sum, o);
    if ((t & 31) == 0) shs[t >> 5] = sum;
    __syncthreads();
    sum = 0.f;
    #pragma unroll
    for (int wgi = 0; wgi < TPB / 32; wgi++) sum += shs[wgi];

    const float inv = __frcp_rn(sum);

    // contiguous float4 stores (plain, cached)
    #pragma unroll
    for (int q = 0; q < VEC4; q++) {
        float4 v;
        v.x = vals[q * 4 + 0] * inv;
        v.y = vals[q * 4 + 1] * inv;
        v.z = vals[q * 4 + 2] * inv;
        v.w = vals[q * 4 + 3] * inv;
        row4[q * TPB + t] = v;
    }
}

// ---------------------------------------------------------------------------
// Inputs: idx[int32 N], emb1_w[f32 N*D], emb2_w[f32 N*D], att_w[f32 2D],
//         att_b[f32 1].  Output: f32 N*N.
// ---------------------------------------------------------------------------
extern "C" void kernel_launch(void* const* d_in, const int* in_sizes, int n_in,
                              void* d_out, int out_size)
{
    const int*   idx  = (const int*)  d_in[0];
    const float* e1   = (const float*)d_in[1];
    const float* e2   = (const float*)d_in[2];
    const float* attw = (const float*)d_in[3];
    const float* attb = (const float*)d_in[4];
    float*       out  = (float*)d_out;

    score_kernel<<<NNODES * 16 / 256, 256>>>(idx, e1, e2, attw);

    // Programmatic dependent launch: softmax blocks spin up while the score
    // kernel drains; the device-side sync enforces the data dependency.
    cudaLaunchConfig_t cfg = {};
    cfg.gridDim  = dim3(NNODES, 1, 1);
    cfg.blockDim = dim3(TPB, 1, 1);
    cfg.dynamicSmemBytes = 0;
    cudaLaunchAttribute attr[1];
    attr[0].id = cudaLaunchAttributeProgrammaticStreamSerialization;
    attr[0].val.programmaticStreamSerializationAllowed = 1;
    cfg.attrs    = attr;
    cfg.numAttrs = 1;
    cudaError_t err = cudaLaunchKernelEx(&cfg, softmax_kernel, attb, out);
    if (err != cudaSuccess) {
        softmax_kernel<<<NNODES, TPB>>>(attb, out);   // identical semantics
    }
}